// round 6
// baseline (speedup 1.0000x reference)
#include <cuda_runtime.h>
#include <cstdint>

#define LQv 2048
#define BZv 8
#define Dv 1024
#define NHv 16
#define NKv 4
#define FFv 2048
#define HDv 64
#define MROWS (LQv * BZv)   // 16384

// ================= scratch (single blob, no allocations) =================
#define MDsz ((size_t)MROWS * Dv)
#define OFF_Q     ((size_t)0)
#define OFF_VAL   (OFF_Q   + MDsz)
#define OFF_OFFA  (OFF_VAL + MDsz)                       // [MROWS,128]
#define OFF_AO    (OFF_OFFA + (size_t)MROWS * 128)
#define OFF_X     (OFF_AO  + MDsz)
#define OFF_Y     (OFF_X   + MDsz)
#define OFF_H     (OFF_Y   + MDsz)                       // [MROWS,FF]
#define OFF_WOFA  (OFF_H   + (size_t)MROWS * FFv)        // [1024,128] row-major
#define OFF_BOFA  (OFF_WOFA + (size_t)Dv * 128)          // [128]
#define SCRATCH_FLOATS (OFF_BOFA + 128)

__device__ float g_scratch[SCRATCH_FLOATS];

__device__ __forceinline__ uint32_t smem_u32(const void* p) {
    uint32_t a;
    asm("{ .reg .u64 t; cvta.to.shared.u64 t, %1; cvt.u32.u64 %0, t; }"
        : "=r"(a) : "l"(p));
    return a;
}
__device__ __forceinline__ uint32_t rn_tf32(float x) {
    uint32_t u;
    asm("cvt.rn.tf32.f32 %0, %1;" : "=r"(u) : "f"(x));
    return u;
}

#define CP16(dst, src) \
    asm volatile("cp.async.cg.shared.global [%0], [%1], 16;" \
                 :: "r"(dst), "l"(src))
#define CP_COMMIT() asm volatile("cp.async.commit_group;")
#define CP_WAIT1()  asm volatile("cp.async.wait_group 1;")
#define CP_WAIT0()  asm volatile("cp.async.wait_group 0;")

// ================= prep: fuse Woff|Wa -> Wofa[K=1024][N=128] =================
__global__ __launch_bounds__(256)
void prep_offa_k(const float* __restrict__ Woff, const float* __restrict__ boff,
                 const float* __restrict__ Wa,   const float* __restrict__ ba,
                 float* __restrict__ Wofa, float* __restrict__ bout)
{
    int idx = blockIdx.x * 256 + threadIdx.x;   // 1024*128
    int k = idx >> 7, n = idx & 127;
    float v = (n < 64) ? Woff[(size_t)k * 64 + n] : Wa[(size_t)k * 64 + (n - 64)];
    Wofa[idx] = v;
    if (idx < 128) bout[idx] = (idx < 64) ? boff[idx] : ba[idx - 64];
}

// ================= elementwise add =================
__global__ __launch_bounds__(256)
void add_k(const float* __restrict__ a, const float* __restrict__ b,
           float* __restrict__ o)
{
    size_t i = ((size_t)blockIdx.x * 256 + threadIdx.x) * 4;
    float4 va = *reinterpret_cast<const float4*>(a + i);
    float4 vb = *reinterpret_cast<const float4*>(b + i);
    float4 vo;
    vo.x = va.x + vb.x; vo.y = va.y + vb.y;
    vo.z = va.z + vb.z; vo.w = va.w + vb.w;
    *reinterpret_cast<float4*>(o + i) = vo;
}

// ================= tf32 mma.sync GEMM, cp.async pipeline =================
// C[M,N] = A[M,K] @ B[K,N] + bias (+epi).
// Template NI: warp tile = 64 x (NI*8); BM=128, BN=NI*32, BK=32, 256 thr.
// 8 warps: 2 in M x 4 in N. SMEM: A [128][36], B [32][BN+8]. 3 stages.
enum { EPI_BIAS = 0, EPI_MASK = 1, EPI_RELU = 2, EPI_RES = 3 };

#define SA 36
#define A_F (128 * SA)            // 4608 floats

__device__ __forceinline__ void mma_tf32(float* c, const uint32_t* a,
                                         const uint32_t* b)
{
    asm volatile(
        "mma.sync.aligned.m16n8k8.row.col.f32.tf32.tf32.f32 "
        "{%0,%1,%2,%3}, {%4,%5,%6,%7}, {%8,%9}, {%0,%1,%2,%3};"
        : "+f"(c[0]), "+f"(c[1]), "+f"(c[2]), "+f"(c[3])
        : "r"(a[0]), "r"(a[1]), "r"(a[2]), "r"(a[3]),
          "r"(b[0]), "r"(b[1]));
}

template <int NI, int EPI>
__global__ __launch_bounds__(256, 1)
void mma_gemm(const float* __restrict__ A, const float* __restrict__ B,
              const float* __restrict__ bias, const float* __restrict__ res,
              const unsigned char* __restrict__ mask,
              int K, int N, float* __restrict__ C)
{
    constexpr int BN  = NI * 32;          // 128 or 256
    constexpr int SB  = BN + 8;           // 136 or 264
    constexpr int B_F = 32 * SB;
    constexpr int STG_F = A_F + B_F;
    constexpr int BCP = BN / 32;          // B cp.async granules per thread (4 or 8)

    extern __shared__ float sm[];
    const uint32_t sb0 = smem_u32(sm);

    const int tid = threadIdx.x;
    const int lane = tid & 31;
    const int wid = tid >> 5;
    const int warp_m = wid & 1;        // 2 warps in M (64 rows each)
    const int warp_n = wid >> 1;       // 4 warps in N (NI*8 cols each)
    const int g = lane >> 2, t = lane & 3;
    const int row0 = blockIdx.y * 128;
    const int col0 = blockIdx.x * BN;

    float acc[4][NI][4];
#pragma unroll
    for (int mi = 0; mi < 4; mi++)
#pragma unroll
        for (int ni = 0; ni < NI; ni++)
#pragma unroll
            for (int j = 0; j < 4; j++) acc[mi][ni][j] = 0.f;

    const int NC = K >> 5;

    auto issue = [&](int c_, int s_) {
        const float* Ap = A + (size_t)row0 * K + (c_ << 5);
        const float* Bp = B + (size_t)(c_ << 5) * N + col0;
        uint32_t ab = sb0 + (uint32_t)s_ * (STG_F * 4);
        uint32_t bb = ab + A_F * 4;
#pragma unroll
        for (int it = 0; it < 4; it++) {
            int id = tid + it * 256;
            int m = id >> 3, kc = id & 7;
            CP16(ab + (uint32_t)(m * SA + kc * 4) * 4,
                 Ap + (size_t)m * K + kc * 4);
        }
#pragma unroll
        for (int it = 0; it < BCP; it++) {
            int id = tid + it * 256;
            int k = id / (BN / 4), nc = id % (BN / 4);
            CP16(bb + (uint32_t)(k * SB + nc * 4) * 4,
                 Bp + (size_t)k * N + nc * 4);
        }
        CP_COMMIT();
    };

    issue(0, 0);
    issue(1, 1);

    for (int c = 0; c < NC; c++) {
        const int s = c % 3;
        if (c + 2 < NC) { CP_WAIT1(); } else { CP_WAIT0(); }
        __syncthreads();
        if (c + 2 < NC) issue(c + 2, (c + 2) % 3);

        const float* as = sm + s * STG_F;
        const float* bs = as + A_F;
#pragma unroll
        for (int kk = 0; kk < 4; kk++) {
            uint32_t af[4][4], bf[NI][2];
#pragma unroll
            for (int mi = 0; mi < 4; mi++) {
                int base = (warp_m * 64 + mi * 16 + g) * SA + kk * 8 + t;
                af[mi][0] = rn_tf32(as[base]);
                af[mi][1] = rn_tf32(as[base + 8 * SA]);
                af[mi][2] = rn_tf32(as[base + 4]);
                af[mi][3] = rn_tf32(as[base + 8 * SA + 4]);
            }
#pragma unroll
            for (int ni = 0; ni < NI; ni++) {
                int bb = (kk * 8 + t) * SB + warp_n * (NI * 8) + ni * 8 + g;
                bf[ni][0] = rn_tf32(bs[bb]);
                bf[ni][1] = rn_tf32(bs[bb + 4 * SB]);
            }
#pragma unroll
            for (int mi = 0; mi < 4; mi++)
#pragma unroll
                for (int ni = 0; ni < NI; ni++)
                    mma_tf32(acc[mi][ni], af[mi], bf[ni]);
        }
    }

    // ---- epilogue ----
#pragma unroll
    for (int mi = 0; mi < 4; mi++) {
        int rA = row0 + warp_m * 64 + mi * 16 + g;     // rows rA, rA+8
#pragma unroll
        for (int half = 0; half < 2; half++) {
            int r = rA + half * 8;
            unsigned char mrow = 0;
            if (EPI == EPI_MASK) {
                int b = r & (BZv - 1);
                int qq = r >> 3;
                mrow = mask[b * LQv + qq];
            }
#pragma unroll
            for (int ni = 0; ni < NI; ni++) {
                int cc = col0 + warp_n * (NI * 8) + ni * 8 + t * 2;
                float v0 = acc[mi][ni][half * 2 + 0] + bias[cc + 0];
                float v1 = acc[mi][ni][half * 2 + 1] + bias[cc + 1];
                if (EPI == EPI_MASK && mrow) { v0 = 0.f; v1 = 0.f; }
                if (EPI == EPI_RELU) { v0 = fmaxf(v0, 0.f); v1 = fmaxf(v1, 0.f); }
                if (EPI == EPI_RES) {
                    float2 rv = *reinterpret_cast<const float2*>(
                        &res[(size_t)r * N + cc]);
                    v0 += rv.x; v1 += rv.y;
                }
                *reinterpret_cast<float2*>(&C[(size_t)r * N + cc]) =
                    make_float2(v0, v1);
            }
        }
    }
}

#define SMB(NI_) ((3 * (A_F + 32 * ((NI_) * 32 + 8))) * 4)

// ================= softmax + grid_sample1d + head combine =================
__global__ __launch_bounds__(256)
void sample_k(const float* __restrict__ value,   // [Lv, BZ, D]
              const float* __restrict__ offa,    // [MROWS, 128]
              const float* __restrict__ refp,    // [BZ, LQ]
              const float* __restrict__ snip,    // [BZ]
              float* __restrict__ out)           // [MROWS, D]
{
    int t = blockIdx.x * 256 + threadIdx.x;
    int c = t & 63;
    int gidx = t >> 6;
    int h = gidx & (NHv - 1);
    int rb = gidx >> 4;
    int b = rb & (BZv - 1);
    int q = rb >> 3;

    const float* ol = offa + (size_t)rb * 128 + h * NKv;
    const float* al = ol + 64;

    float a0 = al[0], a1 = al[1], a2 = al[2], a3 = al[3];
    float m = fmaxf(fmaxf(a0, a1), fmaxf(a2, a3));
    float e0 = __expf(a0 - m), e1 = __expf(a1 - m);
    float e2 = __expf(a2 - m), e3 = __expf(a3 - m);
    float inv_s = 1.f / (e0 + e1 + e2 + e3);
    float ak[4] = {e0 * inv_s, e1 * inv_s, e2 * inv_s, e3 * inv_s};

    float refv = refp[b * LQv + q];
    float inv_sn = 1.f / snip[b];

    float acc = 0.f;
#pragma unroll
    for (int k = 0; k < NKv; k++) {
        float loc = refv + ol[k] * inv_sn;
        float x = loc * (float)(LQv - 1);
        float x0f = floorf(x);
        float w1 = x - x0f;
        float w0 = 1.f - w1;
        float x0c = fminf(fmaxf(x0f, -2.f), (float)(LQv + 1));
        int i0 = (int)x0c;
        int i1 = i0 + 1;
        float v0 = 0.f, v1 = 0.f;
        if (x0f >= 0.f && x0f <= (float)(LQv - 1))
            v0 = value[((size_t)i0 * BZv + b) * Dv + h * HDv + c];
        if (x0f >= -1.f && x0f <= (float)(LQv - 2))
            v1 = value[((size_t)i1 * BZv + b) * Dv + h * HDv + c];
        acc += ak[k] * (w0 * v0 + w1 * v1);
    }
    out[(size_t)rb * Dv + h * HDv + c] = acc;
}

// ================= LayerNorm D=1024 =================
__global__ __launch_bounds__(256)
void ln_k(const float* __restrict__ in, const float* __restrict__ gam,
          const float* __restrict__ bet, float* __restrict__ out)
{
    int row = blockIdx.x;
    const float* xp = in + (size_t)row * Dv;
    int c4 = threadIdx.x * 4;
    float4 v = *reinterpret_cast<const float4*>(&xp[c4]);
    float s  = v.x + v.y + v.z + v.w;
    float ss = v.x * v.x + v.y * v.y + v.z * v.z + v.w * v.w;
#pragma unroll
    for (int o = 16; o > 0; o >>= 1) {
        s  += __shfl_xor_sync(0xffffffffu, s, o);
        ss += __shfl_xor_sync(0xffffffffu, ss, o);
    }
    __shared__ float sh_s[8], sh_ss[8];
    int w = threadIdx.x >> 5;
    if ((threadIdx.x & 31) == 0) { sh_s[w] = s; sh_ss[w] = ss; }
    __syncthreads();
    s = 0.f; ss = 0.f;
#pragma unroll
    for (int i = 0; i < 8; i++) { s += sh_s[i]; ss += sh_ss[i]; }
    float mean = s * (1.f / Dv);
    float var  = ss * (1.f / Dv) - mean * mean;
    float inv  = rsqrtf(var + 1e-5f);
    float4 gv = *reinterpret_cast<const float4*>(&gam[c4]);
    float4 bvv = *reinterpret_cast<const float4*>(&bet[c4]);
    float4 o;
    o.x = (v.x - mean) * inv * gv.x + bvv.x;
    o.y = (v.y - mean) * inv * gv.y + bvv.y;
    o.z = (v.z - mean) * inv * gv.z + bvv.z;
    o.w = (v.w - mean) * inv * gv.w + bvv.w;
    *reinterpret_cast<float4*>(&out[(size_t)row * Dv + c4]) = o;
}

// ================= launch =================
extern "C" void kernel_launch(void* const* d_in, const int* in_sizes, int n_in,
                              void* d_out, int out_size)
{
    const float* src  = (const float*)d_in[0];
    const float* pos  = (const float*)d_in[1];
    const unsigned char* mask = (const unsigned char*)d_in[2];
    const float* refp = (const float*)d_in[3];
    const float* snip = (const float*)d_in[4];
    const float* Wv   = (const float*)d_in[5];
    const float* bv   = (const float*)d_in[6];
    const float* Woff = (const float*)d_in[7];
    const float* boff = (const float*)d_in[8];
    const float* Wa   = (const float*)d_in[9];
    const float* ba   = (const float*)d_in[10];
    const float* Wo   = (const float*)d_in[11];
    const float* bo   = (const float*)d_in[12];
    const float* W1   = (const float*)d_in[13];
    const float* b1   = (const float*)d_in[14];
    const float* W2   = (const float*)d_in[15];
    const float* b2   = (const float*)d_in[16];
    const float* g1   = (const float*)d_in[17];
    const float* be1  = (const float*)d_in[18];
    const float* g2   = (const float*)d_in[19];
    const float* be2  = (const float*)d_in[20];
    float* outp = (float*)d_out;

    float* scratch = nullptr;
    cudaGetSymbolAddress((void**)&scratch, g_scratch);
    float* q    = scratch + OFF_Q;
    float* val  = scratch + OFF_VAL;
    float* offa = scratch + OFF_OFFA;
    float* ao   = scratch + OFF_AO;
    float* x    = scratch + OFF_X;
    float* y    = scratch + OFF_Y;
    float* hh   = scratch + OFF_H;
    float* wofa = scratch + OFF_WOFA;
    float* bofa = scratch + OFF_BOFA;

    cudaFuncSetAttribute(mma_gemm<8, EPI_MASK>,
        cudaFuncAttributeMaxDynamicSharedMemorySize, SMB(8));
    cudaFuncSetAttribute(mma_gemm<4, EPI_BIAS>,
        cudaFuncAttributeMaxDynamicSharedMemorySize, SMB(4));
    cudaFuncSetAttribute(mma_gemm<8, EPI_RELU>,
        cudaFuncAttributeMaxDynamicSharedMemorySize, SMB(8));
    cudaFuncSetAttribute(mma_gemm<8, EPI_RES>,
        cudaFuncAttributeMaxDynamicSharedMemorySize, SMB(8));

    const dim3 blk(256);

    // prep (tiny)
    prep_offa_k<<<(Dv * 128) / 256, blk>>>(Woff, boff, Wa, ba, wofa, bofa);

    // q = src + pos
    add_k<<<(size_t)MROWS * Dv / 4 / 256, blk>>>(src, pos, q);

    // value = src @ Wv + bv (masked)
    mma_gemm<8, EPI_MASK><<<dim3(Dv / 256, MROWS / 128), blk, SMB(8)>>>(
        src, Wv, bv, nullptr, mask, Dv, Dv, val);

    // offsets + attn logits fused: [MROWS,128]
    mma_gemm<4, EPI_BIAS><<<dim3(1, MROWS / 128), blk, SMB(4)>>>(
        q, wofa, bofa, nullptr, nullptr, Dv, 128, offa);

    // softmax + grid-sample + combine
    sample_k<<<(size_t)MROWS * NHv * HDv / 256, blk>>>(val, offa, refp, snip, ao);

    // out proj + residual, LN1
    mma_gemm<8, EPI_RES><<<dim3(Dv / 256, MROWS / 128), blk, SMB(8)>>>(
        ao, Wo, bo, src, nullptr, Dv, Dv, y);
    ln_k<<<MROWS, blk>>>(y, g1, be1, x);

    // FFN
    mma_gemm<8, EPI_RELU><<<dim3(FFv / 256, MROWS / 128), blk, SMB(8)>>>(
        x, W1, b1, nullptr, nullptr, Dv, FFv, hh);
    mma_gemm<8, EPI_RES><<<dim3(Dv / 256, MROWS / 128), blk, SMB(8)>>>(
        hh, W2, b2, x, nullptr, FFv, Dv, y);
    ln_k<<<MROWS, blk>>>(y, g2, be2, outp);
}

// round 8
// speedup vs baseline: 1.0855x; 1.0855x over previous
#include <cuda_runtime.h>
#include <cstdint>

#define LQv 2048
#define BZv 8
#define Dv 1024
#define NHv 16
#define NKv 4
#define FFv 2048
#define HDv 64
#define MROWS (LQv * BZv)   // 16384

// ================= scratch (single blob, no allocations) =================
#define MDsz ((size_t)MROWS * Dv)
#define OFF_Q     ((size_t)0)
#define OFF_VAL   (OFF_Q   + MDsz)
#define OFF_OFFA  (OFF_VAL + MDsz)                       // [MROWS,128]
#define OFF_AO    (OFF_OFFA + (size_t)MROWS * 128)
#define OFF_X     (OFF_AO  + MDsz)
#define OFF_XR    (OFF_X   + MDsz)
#define OFF_Y     (OFF_XR  + MDsz)
#define OFF_H     (OFF_Y   + MDsz)                       // [MROWS,FF]
#define OFF_SRCR  (OFF_H   + (size_t)MROWS * FFv)        // rounded src
#define OFF_WVR   (OFF_SRCR + MDsz)                      // [1024,1024]
#define OFF_WOR   (OFF_WVR + (size_t)Dv * Dv)
#define OFF_W1R   (OFF_WOR + (size_t)Dv * Dv)            // [1024,2048]
#define OFF_W2R   (OFF_W1R + (size_t)Dv * FFv)           // [2048,1024]
#define OFF_WOFA  (OFF_W2R + (size_t)FFv * Dv)           // [1024,128]
#define OFF_BOFA  (OFF_WOFA + (size_t)Dv * 128)          // [128]
#define SCRATCH_FLOATS (OFF_BOFA + 128)

__device__ float g_scratch[SCRATCH_FLOATS];

__device__ __forceinline__ uint32_t smem_u32(const void* p) {
    uint32_t a;
    asm("{ .reg .u64 t; cvta.to.shared.u64 t, %1; cvt.u32.u64 %0, t; }"
        : "=r"(a) : "l"(p));
    return a;
}
__device__ __forceinline__ float rn_tf32f(float x) {
    uint32_t u;
    asm("cvt.rn.tf32.f32 %0, %1;" : "=r"(u) : "f"(x));
    return __uint_as_float(u);
}

#define CP16(dst, src) \
    asm volatile("cp.async.cg.shared.global [%0], [%1], 16;" \
                 :: "r"(dst), "l"(src))
#define CP_COMMIT() asm volatile("cp.async.commit_group;")
#define CP_WAIT0()  asm volatile("cp.async.wait_group 0;")

// ================= round-copy: o[i] = tf32(a[i]) =================
__global__ __launch_bounds__(256)
void round_k(const float* __restrict__ a, float* __restrict__ o)
{
    size_t i = ((size_t)blockIdx.x * 256 + threadIdx.x) * 4;
    float4 v = *reinterpret_cast<const float4*>(a + i);
    v.x = rn_tf32f(v.x); v.y = rn_tf32f(v.y);
    v.z = rn_tf32f(v.z); v.w = rn_tf32f(v.w);
    *reinterpret_cast<float4*>(o + i) = v;
}

// ================= prep: fuse Woff|Wa -> Wofa[K=1024][N=128] (rounded) ======
__global__ __launch_bounds__(256)
void prep_offa_k(const float* __restrict__ Woff, const float* __restrict__ boff,
                 const float* __restrict__ Wa,   const float* __restrict__ ba,
                 float* __restrict__ Wofa, float* __restrict__ bout)
{
    int idx = blockIdx.x * 256 + threadIdx.x;   // 1024*128
    int k = idx >> 7, n = idx & 127;
    float v = (n < 64) ? Woff[(size_t)k * 64 + n] : Wa[(size_t)k * 64 + (n - 64)];
    Wofa[idx] = rn_tf32f(v);
    if (idx < 128) bout[idx] = (idx < 64) ? boff[idx] : ba[idx - 64];
}

// ================= add (rounded output; q only feeds a GEMM) ==============
__global__ __launch_bounds__(256)
void add_k(const float* __restrict__ a, const float* __restrict__ b,
           float* __restrict__ o)
{
    size_t i = ((size_t)blockIdx.x * 256 + threadIdx.x) * 4;
    float4 va = *reinterpret_cast<const float4*>(a + i);
    float4 vb = *reinterpret_cast<const float4*>(b + i);
    float4 vo;
    vo.x = rn_tf32f(va.x + vb.x); vo.y = rn_tf32f(va.y + vb.y);
    vo.z = rn_tf32f(va.z + vb.z); vo.w = rn_tf32f(va.w + vb.w);
    *reinterpret_cast<float4*>(o + i) = vo;
}

// ================= tf32 mma.sync GEMM, 2-stage cp.async, 2 CTA/SM =========
// C[M,N] = A[M,K] @ B[K,N] + bias (+epi). BM=128, BN=128, BK=32, 256 thr.
// Operands are pre-rounded to tf32 — no in-loop cvt.
enum { EPI_BIAS = 0, EPI_MASK = 1, EPI_RELU = 2, EPI_RES = 3 };

#define SA 36
#define SB 136
#define A_F (128 * SA)            // 4608 floats
#define B_F (32 * SB)             // 4352 floats
#define STG_F (A_F + B_F)         // 8960 floats
#define GSMEM_BYTES (2 * STG_F * 4)   // 71680 B

__device__ __forceinline__ void mma_tf32(float* c, const uint32_t* a,
                                         const uint32_t* b)
{
    asm volatile(
        "mma.sync.aligned.m16n8k8.row.col.f32.tf32.tf32.f32 "
        "{%0,%1,%2,%3}, {%4,%5,%6,%7}, {%8,%9}, {%0,%1,%2,%3};"
        : "+f"(c[0]), "+f"(c[1]), "+f"(c[2]), "+f"(c[3])
        : "r"(a[0]), "r"(a[1]), "r"(a[2]), "r"(a[3]),
          "r"(b[0]), "r"(b[1]));
}

template <int EPI>
__global__ __launch_bounds__(256, 2)
void mma_gemm(const float* __restrict__ A, const float* __restrict__ B,
              const float* __restrict__ bias, const float* __restrict__ res,
              const unsigned char* __restrict__ mask,
              int K, int N, float* __restrict__ C)
{
    extern __shared__ float sm[];
    const uint32_t sb0 = smem_u32(sm);

    const int tid = threadIdx.x;
    const int lane = tid & 31;
    const int wid = tid >> 5;
    const int warp_m = wid & 1;        // 2 warps in M (64 rows)
    const int warp_n = wid >> 1;       // 4 warps in N (32 cols)
    const int g = lane >> 2, t = lane & 3;
    const int row0 = blockIdx.y * 128;
    const int col0 = blockIdx.x * 128;

    float acc[4][4][4];
#pragma unroll
    for (int mi = 0; mi < 4; mi++)
#pragma unroll
        for (int ni = 0; ni < 4; ni++)
#pragma unroll
            for (int j = 0; j < 4; j++) acc[mi][ni][j] = 0.f;

    const int NC = K >> 5;

    auto issue = [&](int c_, int s_) {
        const float* Ap = A + (size_t)row0 * K + (c_ << 5);
        const float* Bp = B + (size_t)(c_ << 5) * N + col0;
        uint32_t ab = sb0 + (uint32_t)s_ * (STG_F * 4);
        uint32_t bb = ab + A_F * 4;
#pragma unroll
        for (int it = 0; it < 4; it++) {
            int id = tid + it * 256;
            int m = id >> 3, kc = id & 7;
            CP16(ab + (uint32_t)(m * SA + kc * 4) * 4,
                 Ap + (size_t)m * K + kc * 4);
        }
#pragma unroll
        for (int it = 0; it < 4; it++) {
            int id = tid + it * 256;
            int k = id >> 5, nc = id & 31;
            CP16(bb + (uint32_t)(k * SB + nc * 4) * 4,
                 Bp + (size_t)k * N + nc * 4);
        }
        CP_COMMIT();
    };

    issue(0, 0);

    for (int c = 0; c < NC; c++) {
        CP_WAIT0();
        __syncthreads();
        if (c + 1 < NC) issue(c + 1, (c + 1) & 1);

        const float* as = sm + (c & 1) * STG_F;
        const float* bs = as + A_F;
#pragma unroll
        for (int kk = 0; kk < 4; kk++) {
            uint32_t af[4][4], bf[4][2];
#pragma unroll
            for (int mi = 0; mi < 4; mi++) {
                int base = (warp_m * 64 + mi * 16 + g) * SA + kk * 8 + t;
                af[mi][0] = __float_as_uint(as[base]);
                af[mi][1] = __float_as_uint(as[base + 8 * SA]);
                af[mi][2] = __float_as_uint(as[base + 4]);
                af[mi][3] = __float_as_uint(as[base + 8 * SA + 4]);
            }
#pragma unroll
            for (int ni = 0; ni < 4; ni++) {
                int bb = (kk * 8 + t) * SB + warp_n * 32 + ni * 8 + g;
                bf[ni][0] = __float_as_uint(bs[bb]);
                bf[ni][1] = __float_as_uint(bs[bb + 4 * SB]);
            }
#pragma unroll
            for (int mi = 0; mi < 4; mi++)
#pragma unroll
                for (int ni = 0; ni < 4; ni++)
                    mma_tf32(acc[mi][ni], af[mi], bf[ni]);
        }
    }

    // ---- epilogue ----
#pragma unroll
    for (int mi = 0; mi < 4; mi++) {
        int rA = row0 + warp_m * 64 + mi * 16 + g;     // rows rA, rA+8
#pragma unroll
        for (int half = 0; half < 2; half++) {
            int r = rA + half * 8;
            unsigned char mrow = 0;
            if (EPI == EPI_MASK) {
                int b = r & (BZv - 1);
                int qq = r >> 3;
                mrow = mask[b * LQv + qq];
            }
#pragma unroll
            for (int ni = 0; ni < 4; ni++) {
                int cc = col0 + warp_n * 32 + ni * 8 + t * 2;
                float v0 = acc[mi][ni][half * 2 + 0] + bias[cc + 0];
                float v1 = acc[mi][ni][half * 2 + 1] + bias[cc + 1];
                if (EPI == EPI_MASK && mrow) { v0 = 0.f; v1 = 0.f; }
                if (EPI == EPI_RELU) {
                    // hh only feeds the next GEMM: round to tf32 here
                    v0 = rn_tf32f(fmaxf(v0, 0.f));
                    v1 = rn_tf32f(fmaxf(v1, 0.f));
                }
                if (EPI == EPI_RES) {
                    float2 rv = *reinterpret_cast<const float2*>(
                        &res[(size_t)r * N + cc]);
                    v0 += rv.x; v1 += rv.y;
                }
                *reinterpret_cast<float2*>(&C[(size_t)r * N + cc]) =
                    make_float2(v0, v1);
            }
        }
    }
}

// ================= softmax + grid_sample1d + head combine =================
// ao only feeds the Wo GEMM: output rounded to tf32.
__global__ __launch_bounds__(256)
void sample_k(const float* __restrict__ value,   // [Lv, BZ, D]
              const float* __restrict__ offa,    // [MROWS, 128]
              const float* __restrict__ refp,    // [BZ, LQ]
              const float* __restrict__ snip,    // [BZ]
              float* __restrict__ out)           // [MROWS, D]
{
    int t = blockIdx.x * 256 + threadIdx.x;
    int c = t & 63;
    int gidx = t >> 6;
    int h = gidx & (NHv - 1);
    int rb = gidx >> 4;
    int b = rb & (BZv - 1);
    int q = rb >> 3;

    const float* ol = offa + (size_t)rb * 128 + h * NKv;
    const float* al = ol + 64;

    float a0 = al[0], a1 = al[1], a2 = al[2], a3 = al[3];
    float m = fmaxf(fmaxf(a0, a1), fmaxf(a2, a3));
    float e0 = __expf(a0 - m), e1 = __expf(a1 - m);
    float e2 = __expf(a2 - m), e3 = __expf(a3 - m);
    float inv_s = 1.f / (e0 + e1 + e2 + e3);
    float ak[4] = {e0 * inv_s, e1 * inv_s, e2 * inv_s, e3 * inv_s};

    float refv = refp[b * LQv + q];
    float inv_sn = 1.f / snip[b];

    float acc = 0.f;
#pragma unroll
    for (int k = 0; k < NKv; k++) {
        float loc = refv + ol[k] * inv_sn;
        float x = loc * (float)(LQv - 1);
        float x0f = floorf(x);
        float w1 = x - x0f;
        float w0 = 1.f - w1;
        float x0c = fminf(fmaxf(x0f, -2.f), (float)(LQv + 1));
        int i0 = (int)x0c;
        int i1 = i0 + 1;
        float v0 = 0.f, v1 = 0.f;
        if (x0f >= 0.f && x0f <= (float)(LQv - 1))
            v0 = value[((size_t)i0 * BZv + b) * Dv + h * HDv + c];
        if (x0f >= -1.f && x0f <= (float)(LQv - 2))
            v1 = value[((size_t)i1 * BZv + b) * Dv + h * HDv + c];
        acc += ak[k] * (w0 * v0 + w1 * v1);
    }
    out[(size_t)rb * Dv + h * HDv + c] = rn_tf32f(acc);
}

// ================= LayerNorm D=1024 (optional dual output) ================
__global__ __launch_bounds__(256)
void ln_k(const float* __restrict__ in, const float* __restrict__ gam,
          const float* __restrict__ bet, float* __restrict__ out,
          float* __restrict__ out_r)   // optional rounded copy (may be null)
{
    int row = blockIdx.x;
    const float* xp = in + (size_t)row * Dv;
    int c4 = threadIdx.x * 4;
    float4 v = *reinterpret_cast<const float4*>(&xp[c4]);
    float s  = v.x + v.y + v.z + v.w;
    float ss = v.x * v.x + v.y * v.y + v.z * v.z + v.w * v.w;
#pragma unroll
    for (int o = 16; o > 0; o >>= 1) {
        s  += __shfl_xor_sync(0xffffffffu, s, o);
        ss += __shfl_xor_sync(0xffffffffu, ss, o);
    }
    __shared__ float sh_s[8], sh_ss[8];
    int w = threadIdx.x >> 5;
    if ((threadIdx.x & 31) == 0) { sh_s[w] = s; sh_ss[w] = ss; }
    __syncthreads();
    s = 0.f; ss = 0.f;
#pragma unroll
    for (int i = 0; i < 8; i++) { s += sh_s[i]; ss += sh_ss[i]; }
    float mean = s * (1.f / Dv);
    float var  = ss * (1.f / Dv) - mean * mean;
    float inv  = rsqrtf(var + 1e-5f);
    float4 gv = *reinterpret_cast<const float4*>(&gam[c4]);
    float4 bvv = *reinterpret_cast<const float4*>(&bet[c4]);
    float4 o;
    o.x = (v.x - mean) * inv * gv.x + bvv.x;
    o.y = (v.y - mean) * inv * gv.y + bvv.y;
    o.z = (v.z - mean) * inv * gv.z + bvv.z;
    o.w = (v.w - mean) * inv * gv.w + bvv.w;
    *reinterpret_cast<float4*>(&out[(size_t)row * Dv + c4]) = o;
    if (out_r) {
        float4 r;
        r.x = rn_tf32f(o.x); r.y = rn_tf32f(o.y);
        r.z = rn_tf32f(o.z); r.w = rn_tf32f(o.w);
        *reinterpret_cast<float4*>(&out_r[(size_t)row * Dv + c4]) = r;
    }
}

// ================= launch =================
extern "C" void kernel_launch(void* const* d_in, const int* in_sizes, int n_in,
                              void* d_out, int out_size)
{
    const float* src  = (const float*)d_in[0];
    const float* pos  = (const float*)d_in[1];
    const unsigned char* mask = (const unsigned char*)d_in[2];
    const float* refp = (const float*)d_in[3];
    const float* snip = (const float*)d_in[4];
    const float* Wv   = (const float*)d_in[5];
    const float* bv   = (const float*)d_in[6];
    const float* Woff = (const float*)d_in[7];
    const float* boff = (const float*)d_in[8];
    const float* Wa   = (const float*)d_in[9];
    const float* ba   = (const float*)d_in[10];
    const float* Wo   = (const float*)d_in[11];
    const float* bo   = (const float*)d_in[12];
    const float* W1   = (const float*)d_in[13];
    const float* b1   = (const float*)d_in[14];
    const float* W2   = (const float*)d_in[15];
    const float* b2   = (const float*)d_in[16];
    const float* g1   = (const float*)d_in[17];
    const float* be1  = (const float*)d_in[18];
    const float* g2   = (const float*)d_in[19];
    const float* be2  = (const float*)d_in[20];
    float* outp = (float*)d_out;

    float* scratch = nullptr;
    cudaGetSymbolAddress((void**)&scratch, g_scratch);
    float* q    = scratch + OFF_Q;
    float* val  = scratch + OFF_VAL;
    float* offa = scratch + OFF_OFFA;
    float* ao   = scratch + OFF_AO;
    float* x    = scratch + OFF_X;
    float* xr   = scratch + OFF_XR;
    float* y    = scratch + OFF_Y;
    float* hh   = scratch + OFF_H;
    float* srcr = scratch + OFF_SRCR;
    float* wvr  = scratch + OFF_WVR;
    float* wor  = scratch + OFF_WOR;
    float* w1r  = scratch + OFF_W1R;
    float* w2r  = scratch + OFF_W2R;
    float* wofa = scratch + OFF_WOFA;
    float* bofa = scratch + OFF_BOFA;

    cudaFuncSetAttribute(mma_gemm<EPI_MASK>,
        cudaFuncAttributeMaxDynamicSharedMemorySize, GSMEM_BYTES);
    cudaFuncSetAttribute(mma_gemm<EPI_BIAS>,
        cudaFuncAttributeMaxDynamicSharedMemorySize, GSMEM_BYTES);
    cudaFuncSetAttribute(mma_gemm<EPI_RELU>,
        cudaFuncAttributeMaxDynamicSharedMemorySize, GSMEM_BYTES);
    cudaFuncSetAttribute(mma_gemm<EPI_RES>,
        cudaFuncAttributeMaxDynamicSharedMemorySize, GSMEM_BYTES);

    const dim3 blk(256);

    // ---- prep: pre-round GEMM operands to tf32 ----
    round_k<<<(MDsz / 4) / 256, blk>>>(src, srcr);
    round_k<<<((size_t)Dv * Dv / 4) / 256, blk>>>(Wv, wvr);
    round_k<<<((size_t)Dv * Dv / 4) / 256, blk>>>(Wo, wor);
    round_k<<<((size_t)Dv * FFv / 4) / 256, blk>>>(W1, w1r);
    round_k<<<((size_t)FFv * Dv / 4) / 256, blk>>>(W2, w2r);
    prep_offa_k<<<(Dv * 128) / 256, blk>>>(Woff, boff, Wa, ba, wofa, bofa);

    // q = tf32(src + pos)
    add_k<<<(MDsz / 4) / 256, blk>>>(src, pos, q);

    // value = src @ Wv + bv (masked)
    mma_gemm<EPI_MASK><<<dim3(Dv / 128, MROWS / 128), blk, GSMEM_BYTES>>>(
        srcr, wvr, bv, nullptr, mask, Dv, Dv, val);

    // offsets + attn logits fused: [MROWS,128]
    mma_gemm<EPI_BIAS><<<dim3(1, MROWS / 128), blk, GSMEM_BYTES>>>(
        q, wofa, bofa, nullptr, nullptr, Dv, 128, offa);

    // softmax + grid-sample + combine (rounded out)
    sample_k<<<(size_t)MROWS * NHv * HDv / 256, blk>>>(val, offa, refp, snip, ao);

    // out proj + residual, LN1 (dual out: exact x + rounded xr)
    mma_gemm<EPI_RES><<<dim3(Dv / 128, MROWS / 128), blk, GSMEM_BYTES>>>(
        ao, wor, bo, src, nullptr, Dv, Dv, y);
    ln_k<<<MROWS, blk>>>(y, g1, be1, x, xr);

    // FFN
    mma_gemm<EPI_RELU><<<dim3(FFv / 128, MROWS / 128), blk, GSMEM_BYTES>>>(
        xr, w1r, b1, nullptr, nullptr, Dv, FFv, hh);
    mma_gemm<EPI_RES><<<dim3(Dv / 128, MROWS / 128), blk, GSMEM_BYTES>>>(
        hh, w2r, b2, x, nullptr, FFv, Dv, y);
    ln_k<<<MROWS, blk>>>(y, g2, be2, outp, nullptr);
}